// round 5
// baseline (speedup 1.0000x reference)
#include <cuda_runtime.h>

#define NN 100000
#define EE 800000
#define IF 128
#define HH 64

__device__ __constant__ float SCALE_C = 0.70710678118654752440f;
#define BN_EPS 1e-5f

typedef unsigned long long ull;

// ---- scratch (device globals; no allocations allowed) ----
__device__ float4 g_h4[NN * 16];    // h (in-place across layers), 25.6MB
__device__ float4 g_t4[NN * 16];    // t = (h@w)*norm_out, 25.6MB
__device__ int   g_dego[NN];
__device__ int   g_degi[NN];        // raw in-degree (unclipped) — also CSR row len
__device__ float g_nout[NN];
__device__ float g_nin[NN];
__device__ int   g_rowoff[NN];      // CSR row offsets (by dst)
__device__ int   g_cursor[NN];
__device__ int   g_eidx[EE];        // CSR: src node per slot
__device__ int   g_bsum[128];       // block sums for scan
__device__ float g_sum[HH];
__device__ float g_sumsq[HH];
__device__ float4 g_scale4[HH / 4];
__device__ float4 g_shift4[HH / 4];

__device__ __forceinline__ void ffma2(ull& acc, ull a, ull b) {
    asm("fma.rn.f32x2 %0, %1, %2, %0;" : "+l"(acc) : "l"(a), "l"(b));
}
__device__ __forceinline__ float2 u2f2(ull u) {
    float2 f;
    f.x = __uint_as_float((unsigned)u);
    f.y = __uint_as_float((unsigned)(u >> 32));
    return f;
}

// ---------------------------------------------------------------------------
// setup kernels
__global__ void k_zero() {
    int i = blockIdx.x * blockDim.x + threadIdx.x;
    int stride = gridDim.x * blockDim.x;
    for (int j = i; j < NN; j += stride) { g_dego[j] = 0; g_degi[j] = 0; }
    if (i < HH) { g_sum[i] = 0.f; g_sumsq[i] = 0.f; }
}

__global__ void k_deg(const int* __restrict__ src, const int* __restrict__ dst) {
    int i = blockIdx.x * blockDim.x + threadIdx.x;
    int stride = gridDim.x * blockDim.x;
    for (int e = i; e < EE; e += stride) {
        atomicAdd(&g_dego[src[e]], 1);
        atomicAdd(&g_degi[dst[e]], 1);
    }
}

__global__ void k_norm() {
    int i = blockIdx.x * blockDim.x + threadIdx.x;
    int stride = gridDim.x * blockDim.x;
    for (int j = i; j < NN; j += stride) {
        int dov = g_dego[j]; if (dov < 1) dov = 1;
        int div = g_degi[j]; if (div < 1) div = 1;
        g_nout[j] = rsqrtf((float)dov);
        g_nin[j]  = rsqrtf((float)div);
    }
}

// ---- 3-kernel exclusive scan of g_degi -> g_rowoff ----
__global__ void __launch_bounds__(1024) k_scan1() {
    __shared__ int s[1024];
    int t = threadIdx.x;
    int i = blockIdx.x * 1024 + t;
    int v = (i < NN) ? g_degi[i] : 0;
    s[t] = v;
    __syncthreads();
    #pragma unroll
    for (int off = 1; off < 1024; off <<= 1) {
        int add = (t >= off) ? s[t - off] : 0;
        __syncthreads();
        s[t] += add;
        __syncthreads();
    }
    if (i < NN) g_rowoff[i] = s[t] - v;     // block-local exclusive
    if (t == 1023) g_bsum[blockIdx.x] = s[1023];
}

__global__ void k_scan2(int nblk) {
    __shared__ int s[128];
    int t = threadIdx.x;
    int v = (t < nblk) ? g_bsum[t] : 0;
    s[t] = v;
    __syncthreads();
    #pragma unroll
    for (int off = 1; off < 128; off <<= 1) {
        int add = (t >= off) ? s[t - off] : 0;
        __syncthreads();
        s[t] += add;
        __syncthreads();
    }
    if (t < nblk) g_bsum[t] = s[t] - v;     // exclusive
}

__global__ void k_scan3() {
    int i = blockIdx.x * blockDim.x + threadIdx.x;
    if (i >= NN) return;
    int off = g_rowoff[i] + g_bsum[i >> 10];
    g_rowoff[i] = off;
    g_cursor[i] = off;
}

__global__ void k_bucket(const int* __restrict__ src, const int* __restrict__ dst) {
    int i = blockIdx.x * blockDim.x + threadIdx.x;
    int stride = gridDim.x * blockDim.x;
    for (int e = i; e < EE; e += stride) {
        int d = dst[e];
        int pos = atomicAdd(&g_cursor[d], 1);
        g_eidx[pos] = src[e];
    }
}

// ---------------------------------------------------------------------------
// Register-tiled GEMM with packed f32x2 FMAs.
// C[NN x 64] = A[NN x K] @ W[K x 64]; block = 128 rows, 256 threads (16x16),
// thread tile = 8 rows x 4 cols, accumulated as 4 row-pairs x 4 cols in f32x2.
// FC=true : A = x,     C = acc + bias       -> g_h4
// FC=false: A = g_h4,  C = acc * nout[row]  -> g_t4
template<int K, bool FC>
__global__ void __launch_bounds__(256) k_mm(const float4* __restrict__ A,
                                            const float4* __restrict__ W,
                                            const float* __restrict__ bias) {
    __shared__ __align__(16) float  As[32][128];   // 16KB transposed: As[k][row]
    __shared__ __align__(16) float2 Bd[32][64];    // 16KB duplicated:  (w,w)

    const int tid  = threadIdx.x;
    const int row0 = blockIdx.x * 128;
    const int lrow = tid >> 1;          // 0..127
    const int kq0  = tid & 1;
    const int grow_l = row0 + lrow;
    const bool valid = grow_l < NN;
    const int tx = tid & 15;            // col group (4 cols)
    const int ty = tid >> 4;            // row group (8 rows)

    const float4* Ap = FC ? A : (const float4*)g_h4;

    ull acc[4][4];                      // [row-pair][col] packed f32x2
    #pragma unroll
    for (int p = 0; p < 4; p++)
        #pragma unroll
        for (int c = 0; c < 4; c++) acc[p][c] = 0ULL;

    #pragma unroll 1
    for (int ks = 0; ks < K; ks += 32) {
        // load W chunk [32][64] = 512 float4, 2 per thread; duplicate into Bd
        #pragma unroll
        for (int i = 0; i < 2; i++) {
            int idx = tid + 256 * i;
            int kk = idx >> 4, c4 = idx & 15;
            float4 v = W[(size_t)ks * 16 + idx];
            Bd[kk][4 * c4 + 0] = make_float2(v.x, v.x);
            Bd[kk][4 * c4 + 1] = make_float2(v.y, v.y);
            Bd[kk][4 * c4 + 2] = make_float2(v.z, v.z);
            Bd[kk][4 * c4 + 3] = make_float2(v.w, v.w);
        }
        // load A chunk transposed: rows 0..127, k ks..ks+31
        #pragma unroll
        for (int i = 0; i < 4; i++) {
            int kq = kq0 + 2 * i;       // 0..7 local float4-quad
            float4 v = valid ? Ap[(size_t)grow_l * (K / 4) + (ks >> 2) + kq]
                             : make_float4(0.f, 0.f, 0.f, 0.f);
            As[4 * kq + 0][lrow] = v.x;
            As[4 * kq + 1][lrow] = v.y;
            As[4 * kq + 2][lrow] = v.z;
            As[4 * kq + 3][lrow] = v.w;
        }
        __syncthreads();

        #pragma unroll
        for (int k = 0; k < 32; k++) {
            ull a[4], b[4];
            const ull* arow = (const ull*)&As[k][8 * ty];   // 4 row-pairs
            a[0] = arow[0]; a[1] = arow[1]; a[2] = arow[2]; a[3] = arow[3];
            const ull* brow = (const ull*)&Bd[k][4 * tx];
            b[0] = brow[0]; b[1] = brow[1]; b[2] = brow[2]; b[3] = brow[3];
            #pragma unroll
            for (int p = 0; p < 4; p++)
                #pragma unroll
                for (int c = 0; c < 4; c++)
                    ffma2(acc[p][c], a[p], b[c]);
        }
        __syncthreads();
    }

    #pragma unroll
    for (int p = 0; p < 4; p++) {
        float2 v0 = u2f2(acc[p][0]);
        float2 v1 = u2f2(acc[p][1]);
        float2 v2 = u2f2(acc[p][2]);
        float2 v3 = u2f2(acc[p][3]);
        int r0 = row0 + 8 * ty + 2 * p;
        if (FC) {
            float4 bv = ((const float4*)bias)[tx];
            if (r0 < NN)
                g_h4[(size_t)r0 * 16 + tx] = make_float4(v0.x + bv.x, v1.x + bv.y,
                                                         v2.x + bv.z, v3.x + bv.w);
            if (r0 + 1 < NN)
                g_h4[(size_t)(r0 + 1) * 16 + tx] = make_float4(v0.y + bv.x, v1.y + bv.y,
                                                               v2.y + bv.z, v3.y + bv.w);
        } else {
            if (r0 < NN) {
                float no = g_nout[r0];
                g_t4[(size_t)r0 * 16 + tx] = make_float4(v0.x * no, v1.x * no,
                                                         v2.x * no, v3.x * no);
            }
            if (r0 + 1 < NN) {
                float no = g_nout[r0 + 1];
                g_t4[(size_t)(r0 + 1) * 16 + tx] = make_float4(v0.y * no, v1.y * no,
                                                               v2.y * no, v3.y * no);
            }
        }
    }
}

// ---------------------------------------------------------------------------
// Pull aggregation + fused combine:
//   h[n] = (h[n] + nin[n] * sum_{e: dst=n} t[src_e] + b) * SCALE
// 16 lanes per node (each owns one float4 column). BN=true also accumulates
// per-feature sum / sumsq.
template<bool BN>
__global__ void __launch_bounds__(256) k_pull(const float* __restrict__ b) {
    const int c4 = threadIdx.x & 15;
    const float4 bv = ((const float4*)b)[c4];
    const float sc = SCALE_C;
    float4 ls = make_float4(0.f, 0.f, 0.f, 0.f);
    float4 lq = make_float4(0.f, 0.f, 0.f, 0.f);

    for (int node = blockIdx.x * 16 + (threadIdx.x >> 4); node < NN;
         node += gridDim.x * 16) {
        int start = g_rowoff[node];
        int cnt = g_degi[node];
        float4 a = make_float4(0.f, 0.f, 0.f, 0.f);
        int j = 0;
        for (; j + 1 < cnt; j += 2) {
            int s0 = g_eidx[start + j];
            int s1 = g_eidx[start + j + 1];
            float4 v0 = g_t4[(size_t)s0 * 16 + c4];
            float4 v1 = g_t4[(size_t)s1 * 16 + c4];
            a.x += v0.x + v1.x; a.y += v0.y + v1.y;
            a.z += v0.z + v1.z; a.w += v0.w + v1.w;
        }
        if (j < cnt) {
            int s0 = g_eidx[start + j];
            float4 v0 = g_t4[(size_t)s0 * 16 + c4];
            a.x += v0.x; a.y += v0.y; a.z += v0.z; a.w += v0.w;
        }
        float ni = g_nin[node];
        float4 hv = g_h4[(size_t)node * 16 + c4];
        hv.x = (fmaf(a.x, ni, hv.x) + bv.x) * sc;
        hv.y = (fmaf(a.y, ni, hv.y) + bv.y) * sc;
        hv.z = (fmaf(a.z, ni, hv.z) + bv.z) * sc;
        hv.w = (fmaf(a.w, ni, hv.w) + bv.w) * sc;
        g_h4[(size_t)node * 16 + c4] = hv;
        if (BN) {
            ls.x += hv.x; ls.y += hv.y; ls.z += hv.z; ls.w += hv.w;
            lq.x = fmaf(hv.x, hv.x, lq.x); lq.y = fmaf(hv.y, hv.y, lq.y);
            lq.z = fmaf(hv.z, hv.z, lq.z); lq.w = fmaf(hv.w, hv.w, lq.w);
        }
    }

    if (BN) {
        // lanes l and l^16 share c4 -> pairwise reduce, then cross-warp
        ls.x += __shfl_xor_sync(0xffffffffu, ls.x, 16);
        ls.y += __shfl_xor_sync(0xffffffffu, ls.y, 16);
        ls.z += __shfl_xor_sync(0xffffffffu, ls.z, 16);
        ls.w += __shfl_xor_sync(0xffffffffu, ls.w, 16);
        lq.x += __shfl_xor_sync(0xffffffffu, lq.x, 16);
        lq.y += __shfl_xor_sync(0xffffffffu, lq.y, 16);
        lq.z += __shfl_xor_sync(0xffffffffu, lq.z, 16);
        lq.w += __shfl_xor_sync(0xffffffffu, lq.w, 16);
        __shared__ float4 ss[8][16];
        __shared__ float4 sq[8][16];
        int lane = threadIdx.x & 31, w = threadIdx.x >> 5;
        if (lane < 16) { ss[w][lane] = ls; sq[w][lane] = lq; }
        __syncthreads();
        if (threadIdx.x < 32) {
            int c = threadIdx.x & 15;
            bool isq = threadIdx.x >= 16;
            float4 t = make_float4(0.f, 0.f, 0.f, 0.f);
            #pragma unroll
            for (int ww = 0; ww < 8; ww++) {
                float4 v = isq ? sq[ww][c] : ss[ww][c];
                t.x += v.x; t.y += v.y; t.z += v.z; t.w += v.w;
            }
            float* dstp = isq ? g_sumsq : g_sum;
            atomicAdd(&dstp[4 * c + 0], t.x);
            atomicAdd(&dstp[4 * c + 1], t.y);
            atomicAdd(&dstp[4 * c + 2], t.z);
            atomicAdd(&dstp[4 * c + 3], t.w);
        }
    }
}

// BN finalize: scale/shift per feature
__global__ void k_bnfinal(const float* __restrict__ gamma,
                          const float* __restrict__ beta) {
    int c = threadIdx.x;
    if (c >= HH) return;
    float inv_n = 1.0f / (float)NN;
    float mu = g_sum[c] * inv_n;
    float var = g_sumsq[c] * inv_n - mu * mu;
    float istd = rsqrtf(var + BN_EPS);
    float sc = istd * gamma[c];
    ((float*)g_scale4)[c] = sc;
    ((float*)g_shift4)[c] = beta[c] - mu * sc;
}

// BN apply: out = h * scale + shift
__global__ void __launch_bounds__(256) k_bnapply(float4* __restrict__ out) {
    int i = blockIdx.x * blockDim.x + threadIdx.x;
    int total = NN * 16;
    if (i >= total) return;
    int c4 = i & 15;
    float4 hv = g_h4[i];
    float4 sc = g_scale4[c4];
    float4 sf = g_shift4[c4];
    hv.x = fmaf(hv.x, sc.x, sf.x);
    hv.y = fmaf(hv.y, sc.y, sf.y);
    hv.z = fmaf(hv.z, sc.z, sf.z);
    hv.w = fmaf(hv.w, sc.w, sf.w);
    out[i] = hv;
}

// ---------------------------------------------------------------------------
extern "C" void kernel_launch(void* const* d_in, const int* in_sizes, int n_in,
                              void* d_out, int out_size) {
    const int*   src   = (const int*)d_in[0];
    const int*   dst   = (const int*)d_in[1];
    const float* x     = (const float*)d_in[2];
    const float* fc_w  = (const float*)d_in[3];
    const float* fc_b  = (const float*)d_in[4];
    const float* w1    = (const float*)d_in[5];
    const float* b1    = (const float*)d_in[6];
    const float* w2    = (const float*)d_in[7];
    const float* b2    = (const float*)d_in[8];
    const float* gamma = (const float*)d_in[9];
    const float* beta  = (const float*)d_in[10];
    float4* out = (float4*)d_out;

    const int THREADS = 256;
    const int g_node  = (NN + THREADS - 1) / THREADS;        // 391
    const int g_edge  = (EE + THREADS - 1) / THREADS;        // 3125
    const int g_mm    = (NN + 127) / 128;                    // 782
    const int g_elem  = (NN * 16 + THREADS - 1) / THREADS;   // 6250
    const int g_pullg = 1184;                                // 148*8
    const int nblk_sc = (NN + 1023) / 1024;                  // 98

    k_zero<<<g_node, THREADS>>>();
    k_deg<<<g_edge, THREADS>>>(src, dst);
    k_norm<<<g_node, THREADS>>>();

    // CSR build (by dst)
    k_scan1<<<nblk_sc, 1024>>>();
    k_scan2<<<1, 128>>>(nblk_sc);
    k_scan3<<<g_node, THREADS>>>();
    k_bucket<<<g_edge, THREADS>>>(src, dst);

    // fc
    k_mm<IF, true><<<g_mm, THREADS>>>((const float4*)x, (const float4*)fc_w, fc_b);

    // layer 1
    k_mm<HH, false><<<g_mm, THREADS>>>(nullptr, (const float4*)w1, nullptr);
    k_pull<false><<<g_pullg, THREADS>>>(b1);

    // layer 2
    k_mm<HH, false><<<g_mm, THREADS>>>(nullptr, (const float4*)w2, nullptr);
    k_pull<true><<<g_pullg, THREADS>>>(b2);     // fused BN stats

    // batchnorm
    k_bnfinal<<<1, 64>>>(gamma, beta);
    k_bnapply<<<g_elem, THREADS>>>(out);
}

// round 6
// speedup vs baseline: 1.1949x; 1.1949x over previous
#include <cuda_runtime.h>

#define NN 100000
#define EE 800000
#define IF 128
#define HH 64

__device__ __constant__ float SCALE_C = 0.70710678118654752440f;
#define BN_EPS 1e-5f

// ---- scratch (device globals; no allocations allowed) ----
__device__ float4 g_h4[NN * 16];    // h (in-place across layers), 25.6MB
__device__ float4 g_t4[NN * 16];    // t = (h@w)*norm_out, 25.6MB
__device__ int   g_dego[NN];
__device__ int   g_degi[NN];        // raw in-degree — also CSR row length
__device__ float g_nout[NN];
__device__ float g_nin[NN];
__device__ int   g_rowoff[NN];      // CSR row offsets (by dst)
__device__ int   g_cursor[NN];
__device__ int   g_eidx[EE];        // CSR: src node per slot
__device__ int   g_bsum[128];       // block sums for scan
__device__ float g_sum[HH];
__device__ float g_sumsq[HH];
__device__ float4 g_scale4[HH / 4];
__device__ float4 g_shift4[HH / 4];

// ---------------------------------------------------------------------------
// setup kernels
__global__ void k_zero() {
    int i = blockIdx.x * blockDim.x + threadIdx.x;
    int stride = gridDim.x * blockDim.x;
    for (int j = i; j < NN; j += stride) { g_dego[j] = 0; g_degi[j] = 0; }
    if (i < HH) { g_sum[i] = 0.f; g_sumsq[i] = 0.f; }
}

__global__ void k_deg(const int* __restrict__ src, const int* __restrict__ dst) {
    int i = blockIdx.x * blockDim.x + threadIdx.x;
    int stride = gridDim.x * blockDim.x;
    for (int e = i; e < EE; e += stride) {
        atomicAdd(&g_dego[src[e]], 1);
        atomicAdd(&g_degi[dst[e]], 1);
    }
}

__global__ void k_norm() {
    int i = blockIdx.x * blockDim.x + threadIdx.x;
    int stride = gridDim.x * blockDim.x;
    for (int j = i; j < NN; j += stride) {
        int dov = g_dego[j]; if (dov < 1) dov = 1;
        int div = g_degi[j]; if (div < 1) div = 1;
        g_nout[j] = rsqrtf((float)dov);
        g_nin[j]  = rsqrtf((float)div);
    }
}

// ---- 3-kernel exclusive scan of g_degi -> g_rowoff ----
__global__ void __launch_bounds__(1024) k_scan1() {
    __shared__ int s[1024];
    int t = threadIdx.x;
    int i = blockIdx.x * 1024 + t;
    int v = (i < NN) ? g_degi[i] : 0;
    s[t] = v;
    __syncthreads();
    #pragma unroll
    for (int off = 1; off < 1024; off <<= 1) {
        int add = (t >= off) ? s[t - off] : 0;
        __syncthreads();
        s[t] += add;
        __syncthreads();
    }
    if (i < NN) g_rowoff[i] = s[t] - v;     // block-local exclusive
    if (t == 1023) g_bsum[blockIdx.x] = s[1023];
}

__global__ void k_scan2(int nblk) {
    __shared__ int s[128];
    int t = threadIdx.x;
    int v = (t < nblk) ? g_bsum[t] : 0;
    s[t] = v;
    __syncthreads();
    #pragma unroll
    for (int off = 1; off < 128; off <<= 1) {
        int add = (t >= off) ? s[t - off] : 0;
        __syncthreads();
        s[t] += add;
        __syncthreads();
    }
    if (t < nblk) g_bsum[t] = s[t] - v;     // exclusive
}

__global__ void k_scan3() {
    int i = blockIdx.x * blockDim.x + threadIdx.x;
    if (i >= NN) return;
    int off = g_rowoff[i] + g_bsum[i >> 10];
    g_rowoff[i] = off;
    g_cursor[i] = off;
}

__global__ void k_bucket(const int* __restrict__ src, const int* __restrict__ dst) {
    int i = blockIdx.x * blockDim.x + threadIdx.x;
    int stride = gridDim.x * blockDim.x;
    for (int e = i; e < EE; e += stride) {
        int d = dst[e];
        int pos = atomicAdd(&g_cursor[d], 1);
        g_eidx[pos] = src[e];
    }
}

// ---------------------------------------------------------------------------
// Register-tiled GEMM (round-4 proven version): C[NN x 64] = A[NN x K] @ W[K x 64]
// block = 128 rows, 256 threads (16x16), thread tile = 8 rows x 4 cols.
// FC=true : A = x,     C = acc + bias       -> g_h4
// FC=false: A = g_h4,  C = acc * nout[row]  -> g_t4
template<int K, bool FC>
__global__ void __launch_bounds__(256) k_mm(const float4* __restrict__ A,
                                            const float4* __restrict__ W,
                                            const float* __restrict__ bias) {
    __shared__ float As[32][128];   // 16KB, transposed chunk: As[k][row]
    __shared__ float Bs[32][64];    //  8KB

    const int tid  = threadIdx.x;
    const int row0 = blockIdx.x * 128;
    const int lrow = tid >> 1;          // 0..127
    const int kq0  = tid & 1;
    const int grow_l = row0 + lrow;
    const bool valid = grow_l < NN;
    const int tx = tid & 15;            // col group (4 cols)
    const int ty = tid >> 4;            // row group (8 rows)

    const float4* Ap = FC ? A : (const float4*)g_h4;

    float acc[8][4];
    #pragma unroll
    for (int r = 0; r < 8; r++)
        #pragma unroll
        for (int c = 0; c < 4; c++) acc[r][c] = 0.f;

    #pragma unroll 1
    for (int ks = 0; ks < K; ks += 32) {
        #pragma unroll
        for (int i = 0; i < 2; i++) {
            int idx = tid + 256 * i;
            ((float4*)Bs)[idx] = W[(size_t)ks * 16 + idx];
        }
        #pragma unroll
        for (int i = 0; i < 4; i++) {
            int kq = kq0 + 2 * i;       // 0..7 (local quad)
            float4 v = valid ? Ap[(size_t)grow_l * (K / 4) + (ks >> 2) + kq]
                             : make_float4(0.f, 0.f, 0.f, 0.f);
            As[4 * kq + 0][lrow] = v.x;
            As[4 * kq + 1][lrow] = v.y;
            As[4 * kq + 2][lrow] = v.z;
            As[4 * kq + 3][lrow] = v.w;
        }
        __syncthreads();

        #pragma unroll
        for (int k = 0; k < 32; k++) {
            float4 a0 = *(const float4*)&As[k][8 * ty];
            float4 a1 = *(const float4*)&As[k][8 * ty + 4];
            float4 b  = *(const float4*)&Bs[k][4 * tx];
            float av[8] = {a0.x, a0.y, a0.z, a0.w, a1.x, a1.y, a1.z, a1.w};
            float bv[4] = {b.x, b.y, b.z, b.w};
            #pragma unroll
            for (int r = 0; r < 8; r++)
                #pragma unroll
                for (int c = 0; c < 4; c++)
                    acc[r][c] = fmaf(av[r], bv[c], acc[r][c]);
        }
        __syncthreads();
    }

    if (FC) {
        float4 bv = ((const float4*)bias)[tx];
        #pragma unroll
        for (int r = 0; r < 8; r++) {
            int grow = row0 + 8 * ty + r;
            if (grow < NN) {
                float4 o = make_float4(acc[r][0] + bv.x, acc[r][1] + bv.y,
                                       acc[r][2] + bv.z, acc[r][3] + bv.w);
                g_h4[(size_t)grow * 16 + tx] = o;
            }
        }
    } else {
        #pragma unroll
        for (int r = 0; r < 8; r++) {
            int grow = row0 + 8 * ty + r;
            if (grow < NN) {
                float no = g_nout[grow];
                float4 o = make_float4(acc[r][0] * no, acc[r][1] * no,
                                       acc[r][2] * no, acc[r][3] * no);
                g_t4[(size_t)grow * 16 + tx] = o;
            }
        }
    }
}

// ---------------------------------------------------------------------------
// Pull aggregation v2: ONE WARP PER NODE.
// lane = 16*eslot + c4; the two eslot halves process interleaved edges, giving
// 4 independent row gathers in flight per warp per unrolled iteration.
//   h[n] = (h[n] + nin[n] * sum_{e: dst=n} t[src_e] + b) * SCALE
template<bool BN>
__global__ void __launch_bounds__(256) k_pull(const float* __restrict__ b) {
    const int lane  = threadIdx.x & 31;
    const int c4    = lane & 15;
    const int eslot = lane >> 4;        // 0 or 1
    const int wid   = threadIdx.x >> 5; // 0..7
    const float4 bv = ((const float4*)b)[c4];
    const float sc = SCALE_C;
    float4 ls = make_float4(0.f, 0.f, 0.f, 0.f);
    float4 lq = make_float4(0.f, 0.f, 0.f, 0.f);

    for (int node = blockIdx.x * 8 + wid; node < NN; node += gridDim.x * 8) {
        const int start = g_rowoff[node];
        const int cnt   = g_degi[node];
        float4 a = make_float4(0.f, 0.f, 0.f, 0.f);

        int j = eslot;
        // main loop: each slot handles edges j and j+2 -> 4 edges/warp/iter
        for (; j + 2 < cnt; j += 4) {
            int s0 = __ldg(&g_eidx[start + j]);
            int s1 = __ldg(&g_eidx[start + j + 2]);
            float4 v0 = g_t4[(size_t)s0 * 16 + c4];
            float4 v1 = g_t4[(size_t)s1 * 16 + c4];
            a.x += v0.x + v1.x; a.y += v0.y + v1.y;
            a.z += v0.z + v1.z; a.w += v0.w + v1.w;
        }
        if (j < cnt) {
            int s0 = __ldg(&g_eidx[start + j]);
            float4 v0 = g_t4[(size_t)s0 * 16 + c4];
            a.x += v0.x; a.y += v0.y; a.z += v0.z; a.w += v0.w;
            j += 2;
            if (j < cnt) {
                int s1 = __ldg(&g_eidx[start + j]);
                float4 v1 = g_t4[(size_t)s1 * 16 + c4];
                a.x += v1.x; a.y += v1.y; a.z += v1.z; a.w += v1.w;
            }
        }
        // merge the two edge-slots (lane and lane^16 share c4)
        a.x += __shfl_xor_sync(0xffffffffu, a.x, 16);
        a.y += __shfl_xor_sync(0xffffffffu, a.y, 16);
        a.z += __shfl_xor_sync(0xffffffffu, a.z, 16);
        a.w += __shfl_xor_sync(0xffffffffu, a.w, 16);

        if (eslot == 0) {
            float ni = g_nin[node];
            float4 hv = g_h4[(size_t)node * 16 + c4];
            hv.x = (fmaf(a.x, ni, hv.x) + bv.x) * sc;
            hv.y = (fmaf(a.y, ni, hv.y) + bv.y) * sc;
            hv.z = (fmaf(a.z, ni, hv.z) + bv.z) * sc;
            hv.w = (fmaf(a.w, ni, hv.w) + bv.w) * sc;
            g_h4[(size_t)node * 16 + c4] = hv;
            if (BN) {
                ls.x += hv.x; ls.y += hv.y; ls.z += hv.z; ls.w += hv.w;
                lq.x = fmaf(hv.x, hv.x, lq.x); lq.y = fmaf(hv.y, hv.y, lq.y);
                lq.z = fmaf(hv.z, hv.z, lq.z); lq.w = fmaf(hv.w, hv.w, lq.w);
            }
        }
    }

    if (BN) {
        // eslot1 lanes hold zeros; the xor-16 add is a no-op for them
        ls.x += __shfl_xor_sync(0xffffffffu, ls.x, 16);
        ls.y += __shfl_xor_sync(0xffffffffu, ls.y, 16);
        ls.z += __shfl_xor_sync(0xffffffffu, ls.z, 16);
        ls.w += __shfl_xor_sync(0xffffffffu, ls.w, 16);
        lq.x += __shfl_xor_sync(0xffffffffu, lq.x, 16);
        lq.y += __shfl_xor_sync(0xffffffffu, lq.y, 16);
        lq.z += __shfl_xor_sync(0xffffffffu, lq.z, 16);
        lq.w += __shfl_xor_sync(0xffffffffu, lq.w, 16);
        __shared__ float4 ss[8][16];
        __shared__ float4 sq[8][16];
        if (lane < 16) { ss[wid][lane] = ls; sq[wid][lane] = lq; }
        __syncthreads();
        if (threadIdx.x < 32) {
            int c = threadIdx.x & 15;
            bool isq = threadIdx.x >= 16;
            float4 t = make_float4(0.f, 0.f, 0.f, 0.f);
            #pragma unroll
            for (int ww = 0; ww < 8; ww++) {
                float4 v = isq ? sq[ww][c] : ss[ww][c];
                t.x += v.x; t.y += v.y; t.z += v.z; t.w += v.w;
            }
            float* dstp = isq ? g_sumsq : g_sum;
            atomicAdd(&dstp[4 * c + 0], t.x);
            atomicAdd(&dstp[4 * c + 1], t.y);
            atomicAdd(&dstp[4 * c + 2], t.z);
            atomicAdd(&dstp[4 * c + 3], t.w);
        }
    }
}

// BN finalize: scale/shift per feature
__global__ void k_bnfinal(const float* __restrict__ gamma,
                          const float* __restrict__ beta) {
    int c = threadIdx.x;
    if (c >= HH) return;
    float inv_n = 1.0f / (float)NN;
    float mu = g_sum[c] * inv_n;
    float var = g_sumsq[c] * inv_n - mu * mu;
    float istd = rsqrtf(var + BN_EPS);
    float sc = istd * gamma[c];
    ((float*)g_scale4)[c] = sc;
    ((float*)g_shift4)[c] = beta[c] - mu * sc;
}

// BN apply: out = h * scale + shift
__global__ void __launch_bounds__(256) k_bnapply(float4* __restrict__ out) {
    int i = blockIdx.x * blockDim.x + threadIdx.x;
    int total = NN * 16;
    if (i >= total) return;
    int c4 = i & 15;
    float4 hv = g_h4[i];
    float4 sc = g_scale4[c4];
    float4 sf = g_shift4[c4];
    hv.x = fmaf(hv.x, sc.x, sf.x);
    hv.y = fmaf(hv.y, sc.y, sf.y);
    hv.z = fmaf(hv.z, sc.z, sf.z);
    hv.w = fmaf(hv.w, sc.w, sf.w);
    out[i] = hv;
}

// ---------------------------------------------------------------------------
extern "C" void kernel_launch(void* const* d_in, const int* in_sizes, int n_in,
                              void* d_out, int out_size) {
    const int*   src   = (const int*)d_in[0];
    const int*   dst   = (const int*)d_in[1];
    const float* x     = (const float*)d_in[2];
    const float* fc_w  = (const float*)d_in[3];
    const float* fc_b  = (const float*)d_in[4];
    const float* w1    = (const float*)d_in[5];
    const float* b1    = (const float*)d_in[6];
    const float* w2    = (const float*)d_in[7];
    const float* b2    = (const float*)d_in[8];
    const float* gamma = (const float*)d_in[9];
    const float* beta  = (const float*)d_in[10];
    float4* out = (float4*)d_out;

    const int THREADS = 256;
    const int g_node  = (NN + THREADS - 1) / THREADS;        // 391
    const int g_edge  = (EE + THREADS - 1) / THREADS;        // 3125
    const int g_mm    = (NN + 127) / 128;                    // 782
    const int g_elem  = (NN * 16 + THREADS - 1) / THREADS;   // 6250
    const int g_pullg = 2048;                                // 16384 warp-slots
    const int nblk_sc = (NN + 1023) / 1024;                  // 98

    // Launch order arranged so ncu (-s 5 -c 1) profiles the 6th launch = mm64.
    k_zero<<<g_node, THREADS>>>();
    k_deg<<<g_edge, THREADS>>>(src, dst);
    k_norm<<<g_node, THREADS>>>();
    k_scan1<<<nblk_sc, 1024>>>();
    k_mm<IF, true><<<g_mm, THREADS>>>((const float4*)x, (const float4*)fc_w, fc_b);   // 5th
    k_mm<HH, false><<<g_mm, THREADS>>>(nullptr, (const float4*)w1, nullptr);          // 6th (profiled)
    k_scan2<<<1, 128>>>(nblk_sc);
    k_scan3<<<g_node, THREADS>>>();
    k_bucket<<<g_edge, THREADS>>>(src, dst);

    // layer 1 aggregation
    k_pull<false><<<g_pullg, THREADS>>>(b1);

    // layer 2
    k_mm<HH, false><<<g_mm, THREADS>>>(nullptr, (const float4*)w2, nullptr);
    k_pull<true><<<g_pullg, THREADS>>>(b2);     // fused BN stats

    // batchnorm
    k_bnfinal<<<1, 64>>>(gamma, beta);
    k_bnapply<<<g_elem, THREADS>>>(out);
}